// round 11
// baseline (speedup 1.0000x reference)
#include <cuda_runtime.h>
#include <math.h>

#define N_ROWS 8192
#define N_COLS 512
#define GRID_A 512
#define THREADS_A 256
#define WARPS_A 8              /* 512 blocks * 8 warps * 2 rows = 8192 rows */
#define NREP 16                /* column replicas  */
#define SREP 64                /* scalar replicas  */

#define SCALE_F     4294967296.0f        /* 2^32, exact in float */
#define INV_SCALE_F (1.0f / 4294967296.0f)

// Order-invariant integer accumulators (zero-init; last block resets).
__device__ unsigned long long g_col_ll[NREP][N_COLS];
__device__ unsigned long long g_S_ll[SREP];
__device__ int g_max_int[SREP];          // bit-cast float, values >= 0
__device__ unsigned int g_counter;

__global__ void __launch_bounds__(THREADS_A)
fused_loss_kernel(const float* __restrict__ x, float* __restrict__ out) {
    __shared__ float s_colw[WARPS_A][N_COLS];   // 16 KB
    __shared__ float s_w[WARPS_A];
    __shared__ float s_sm[2];
    __shared__ float s_mx[2];
    __shared__ unsigned int s_last;

    const int tid = threadIdx.x;
    const int wid = tid >> 5;
    const int lid = tid & 31;

    // ---- warp owns 2 rows; 8 named float4 loads, all issued up front ----
    const int row0 = (blockIdx.x * WARPS_A + wid) * 2;
    const float4* p0 = reinterpret_cast<const float4*>(x + (size_t)row0 * N_COLS);
    const float4* p1 = p0 + 128;

    const float4 a0 = p0[lid];      const float4 a1 = p0[32 + lid];
    const float4 a2 = p0[64 + lid]; const float4 a3 = p0[96 + lid];
    const float4 b0 = p1[lid];      const float4 b1 = p1[32 + lid];
    const float4 b2 = p1[64 + lid]; const float4 b3 = p1[96 + lid];

    // column partials into smem (vectorized, conflict-free)
    float4 c0, c1, c2, c3;
    c0.x = a0.x + b0.x; c0.y = a0.y + b0.y; c0.z = a0.z + b0.z; c0.w = a0.w + b0.w;
    c1.x = a1.x + b1.x; c1.y = a1.y + b1.y; c1.z = a1.z + b1.z; c1.w = a1.w + b1.w;
    c2.x = a2.x + b2.x; c2.y = a2.y + b2.y; c2.z = a2.z + b2.z; c2.w = a2.w + b2.w;
    c3.x = a3.x + b3.x; c3.y = a3.y + b3.y; c3.z = a3.z + b3.z; c3.w = a3.w + b3.w;
    *reinterpret_cast<float4*>(&s_colw[wid][0   + lid * 4]) = c0;
    *reinterpret_cast<float4*>(&s_colw[wid][128 + lid * 4]) = c1;
    *reinterpret_cast<float4*>(&s_colw[wid][256 + lid * 4]) = c2;
    *reinterpret_cast<float4*>(&s_colw[wid][384 + lid * 4]) = c3;

    float sq0 = a0.x*a0.x + a0.y*a0.y + a0.z*a0.z + a0.w*a0.w
              + a1.x*a1.x + a1.y*a1.y + a1.z*a1.z + a1.w*a1.w
              + a2.x*a2.x + a2.y*a2.y + a2.z*a2.z + a2.w*a2.w
              + a3.x*a3.x + a3.y*a3.y + a3.z*a3.z + a3.w*a3.w;
    float sq1 = b0.x*b0.x + b0.y*b0.y + b0.z*b0.z + b0.w*b0.w
              + b1.x*b1.x + b1.y*b1.y + b1.z*b1.z + b1.w*b1.w
              + b2.x*b2.x + b2.y*b2.y + b2.z*b2.z + b2.w*b2.w
              + b3.x*b3.x + b3.y*b3.y + b3.z*b3.z + b3.w*b3.w;

    #pragma unroll
    for (int off = 16; off > 0; off >>= 1) {
        sq0 += __shfl_xor_sync(0xffffffffu, sq0, off);
        sq1 += __shfl_xor_sync(0xffffffffu, sq1, off);
    }
    // fire-and-forget RED: per-warp S and max (replicated)
    if (lid == 0) {
        const int rs = (blockIdx.x * WARPS_A + wid) & (SREP - 1);
        atomicAdd(&g_S_ll[rs],
                  (unsigned long long)__float2ll_rn((sq0 + sq1) * SCALE_F));
        atomicMax(&g_max_int[rs], __float_as_int(fmaxf(sq0, sq1)));
    }
    __syncthreads();

    // ---- combine 8 warps, push column REDs (fire-and-forget) ----
    const int rep = blockIdx.x & (NREP - 1);
    #pragma unroll
    for (int k = 0; k < 2; ++k) {
        const int c = tid + k * THREADS_A;
        float v = 0.f;
        #pragma unroll
        for (int w = 0; w < WARPS_A; ++w) v += s_colw[w][c];
        atomicAdd(&g_col_ll[rep][c],
                  (unsigned long long)__float2ll_rn(v * SCALE_F));
    }

    // ---- last-block-done election ----
    if (tid == 0) {
        __threadfence();   // release: my REDs visible before counter bump
        const unsigned int prev = atomicAdd(&g_counter, 1u);
        s_last = (prev == (unsigned int)(GRID_A - 1)) ? 1u : 0u;
    }
    __syncthreads();
    if (s_last == 0u) return;

    // ---- finalize (last block only): all-float, log-depth ----
    __threadfence();       // acquire: see all blocks' REDs

    // column totals: thread owns cols tid and tid+256 (32 indep L2 loads)
    long long t0 = 0ll, t1 = 0ll;
    #pragma unroll
    for (int r = 0; r < NREP; ++r) {
        t0 += (long long)g_col_ll[r][tid];
        t1 += (long long)g_col_ll[r][tid + THREADS_A];
    }
    const float f0 = (float)t0 * INV_SCALE_F;
    const float f1 = (float)t1 * INV_SCALE_F;
    float csq = f0 * f0 + f1 * f1;

    #pragma unroll
    for (int off = 16; off > 0; off >>= 1)
        csq += __shfl_xor_sync(0xffffffffu, csq, off);
    if (lid == 0) s_w[wid] = csq;

    // S and max from replicated scalars (warps 0 and 1)
    if (tid < SREP) {
        float Sp = (float)(long long)g_S_ll[tid] * INV_SCALE_F;
        float Mp = __int_as_float(g_max_int[tid]);
        #pragma unroll
        for (int off = 16; off > 0; off >>= 1) {
            Sp += __shfl_xor_sync(0xffffffffu, Sp, off);
            Mp = fmaxf(Mp, __shfl_xor_sync(0xffffffffu, Mp, off));
        }
        if (lid == 0) { s_sm[wid] = Sp; s_mx[wid] = Mp; }
    }
    __syncthreads();

    if (wid == 0) {
        float w = (lid < WARPS_A) ? s_w[lid] : 0.f;
        #pragma unroll
        for (int off = 4; off > 0; off >>= 1)
            w += __shfl_xor_sync(0xffffffffu, w, off);
        if (lid == 0) {
            const float ssq_total = w;
            const float S_total = s_sm[0] + s_sm[1];
            const float maxsq = fmaxf(s_mx[0], s_mx[1]);
            const float numer = 8192.0f * S_total - ssq_total;
            const float norm = sqrtf(maxsq);
            const float count = 0.5f * (float)N_ROWS * (float)(N_ROWS - 1);
            out[0] = numer / (norm * count);
        }
    }
    // reads done (barrier above covered s_w/s_sm; column reads are per-thread
    // and complete before these stores in program order) -> reset everything
    #pragma unroll
    for (int r = 0; r < NREP; ++r) {
        g_col_ll[r][tid] = 0ull;
        g_col_ll[r][tid + THREADS_A] = 0ull;
    }
    if (tid < SREP) {
        g_S_ll[tid] = 0ull;
        g_max_int[tid] = 0;
    }
    if (tid == 0) g_counter = 0u;
}

extern "C" void kernel_launch(void* const* d_in, const int* in_sizes, int n_in,
                              void* d_out, int out_size) {
    (void)in_sizes; (void)n_in; (void)out_size;
    const float* x = (const float*)d_in[0];
    float* out = (float*)d_out;
    fused_loss_kernel<<<GRID_A, THREADS_A>>>(x, out);
}

// round 12
// speedup vs baseline: 1.1990x; 1.1990x over previous
#include <cuda_runtime.h>
#include <math.h>

#define N_ROWS 8192
#define N_COLS 512
#define GRID_A 512
#define THREADS_A 256
#define WARPS_A 8              /* 512 blocks * 8 warps * 2 rows = 8192 rows */
#define NREP 16                /* column replicas  */
#define SREP 64                /* scalar replicas  */

// Float accumulators (zero-init; last block resets).
__device__ float g_col[NREP][N_COLS];
__device__ float g_S[SREP];
__device__ int g_max_int[SREP];          // bit-cast float, values >= 0
__device__ unsigned int g_counter;

__global__ void __launch_bounds__(THREADS_A)
fused_loss_kernel(const float* __restrict__ x, float* __restrict__ out) {
    __shared__ float s_colw[WARPS_A][N_COLS];   // 16 KB
    __shared__ float s_w[WARPS_A];
    __shared__ float s_sm[2];
    __shared__ float s_mx[2];
    __shared__ unsigned int s_last;

    const int tid = threadIdx.x;
    const int wid = tid >> 5;
    const int lid = tid & 31;

    // ---- warp owns 2 rows; 8 named float4 loads, all issued up front ----
    const int row0 = (blockIdx.x * WARPS_A + wid) * 2;
    const float4* p0 = reinterpret_cast<const float4*>(x + (size_t)row0 * N_COLS);
    const float4* p1 = p0 + 128;

    const float4 a0 = p0[lid];      const float4 a1 = p0[32 + lid];
    const float4 a2 = p0[64 + lid]; const float4 a3 = p0[96 + lid];
    const float4 b0 = p1[lid];      const float4 b1 = p1[32 + lid];
    const float4 b2 = p1[64 + lid]; const float4 b3 = p1[96 + lid];

    // column partials into smem (vectorized, conflict-free)
    float4 c0, c1, c2, c3;
    c0.x = a0.x + b0.x; c0.y = a0.y + b0.y; c0.z = a0.z + b0.z; c0.w = a0.w + b0.w;
    c1.x = a1.x + b1.x; c1.y = a1.y + b1.y; c1.z = a1.z + b1.z; c1.w = a1.w + b1.w;
    c2.x = a2.x + b2.x; c2.y = a2.y + b2.y; c2.z = a2.z + b2.z; c2.w = a2.w + b2.w;
    c3.x = a3.x + b3.x; c3.y = a3.y + b3.y; c3.z = a3.z + b3.z; c3.w = a3.w + b3.w;
    *reinterpret_cast<float4*>(&s_colw[wid][0   + lid * 4]) = c0;
    *reinterpret_cast<float4*>(&s_colw[wid][128 + lid * 4]) = c1;
    *reinterpret_cast<float4*>(&s_colw[wid][256 + lid * 4]) = c2;
    *reinterpret_cast<float4*>(&s_colw[wid][384 + lid * 4]) = c3;

    float sq0 = a0.x*a0.x + a0.y*a0.y + a0.z*a0.z + a0.w*a0.w
              + a1.x*a1.x + a1.y*a1.y + a1.z*a1.z + a1.w*a1.w
              + a2.x*a2.x + a2.y*a2.y + a2.z*a2.z + a2.w*a2.w
              + a3.x*a3.x + a3.y*a3.y + a3.z*a3.z + a3.w*a3.w;
    float sq1 = b0.x*b0.x + b0.y*b0.y + b0.z*b0.z + b0.w*b0.w
              + b1.x*b1.x + b1.y*b1.y + b1.z*b1.z + b1.w*b1.w
              + b2.x*b2.x + b2.y*b2.y + b2.z*b2.z + b2.w*b2.w
              + b3.x*b3.x + b3.y*b3.y + b3.z*b3.z + b3.w*b3.w;

    #pragma unroll
    for (int off = 16; off > 0; off >>= 1) {
        sq0 += __shfl_xor_sync(0xffffffffu, sq0, off);
        sq1 += __shfl_xor_sync(0xffffffffu, sq1, off);
    }
    // fire-and-forget float REDs: per-warp S and max (replicated)
    if (lid == 0) {
        const int rs = (blockIdx.x * WARPS_A + wid) & (SREP - 1);
        atomicAdd(&g_S[rs], sq0 + sq1);
        atomicMax(&g_max_int[rs], __float_as_int(fmaxf(sq0, sq1)));
    }
    __syncthreads();

    // ---- combine 8 warps, push float column REDs (fire-and-forget) ----
    const int rep = blockIdx.x & (NREP - 1);
    #pragma unroll
    for (int k = 0; k < 2; ++k) {
        const int c = tid + k * THREADS_A;
        float v = 0.f;
        #pragma unroll
        for (int w = 0; w < WARPS_A; ++w) v += s_colw[w][c];
        atomicAdd(&g_col[rep][c], v);
    }

    // ---- last-block-done election ----
    if (tid == 0) {
        __threadfence();   // release: my REDs visible before counter bump
        const unsigned int prev = atomicAdd(&g_counter, 1u);
        s_last = (prev == (unsigned int)(GRID_A - 1)) ? 1u : 0u;
    }
    __syncthreads();
    if (s_last == 0u) return;

    // ---- finalize (last block only): all-float, log-depth ----
    __threadfence();       // acquire: see all blocks' REDs

    // column totals: thread owns cols tid and tid+256 (32 indep L2 loads)
    float f0 = 0.f, f1 = 0.f;
    #pragma unroll
    for (int r = 0; r < NREP; ++r) {
        f0 += g_col[r][tid];
        f1 += g_col[r][tid + THREADS_A];
    }
    float csq = f0 * f0 + f1 * f1;

    #pragma unroll
    for (int off = 16; off > 0; off >>= 1)
        csq += __shfl_xor_sync(0xffffffffu, csq, off);
    if (lid == 0) s_w[wid] = csq;

    // S and max from replicated scalars (warps 0 and 1)
    if (tid < SREP) {
        float Sp = g_S[tid];
        float Mp = __int_as_float(g_max_int[tid]);
        #pragma unroll
        for (int off = 16; off > 0; off >>= 1) {
            Sp += __shfl_xor_sync(0xffffffffu, Sp, off);
            Mp = fmaxf(Mp, __shfl_xor_sync(0xffffffffu, Mp, off));
        }
        if (lid == 0) { s_sm[wid] = Sp; s_mx[wid] = Mp; }
    }
    __syncthreads();

    if (wid == 0) {
        float w = (lid < WARPS_A) ? s_w[lid] : 0.f;
        #pragma unroll
        for (int off = 4; off > 0; off >>= 1)
            w += __shfl_xor_sync(0xffffffffu, w, off);
        if (lid == 0) {
            const float ssq_total = w;
            const float S_total = s_sm[0] + s_sm[1];
            const float maxsq = fmaxf(s_mx[0], s_mx[1]);
            const float numer = 8192.0f * S_total - ssq_total;
            const float norm = sqrtf(maxsq);
            const float count = 0.5f * (float)N_ROWS * (float)(N_ROWS - 1);
            out[0] = numer / (norm * count);
        }
    }
    // reset accumulators for next graph replay
    #pragma unroll
    for (int r = 0; r < NREP; ++r) {
        g_col[r][tid] = 0.f;
        g_col[r][tid + THREADS_A] = 0.f;
    }
    if (tid < SREP) {
        g_S[tid] = 0.f;
        g_max_int[tid] = 0;
    }
    if (tid == 0) g_counter = 0u;
}

extern "C" void kernel_launch(void* const* d_in, const int* in_sizes, int n_in,
                              void* d_out, int out_size) {
    (void)in_sizes; (void)n_in; (void)out_size;
    const float* x = (const float*)d_in[0];
    float* out = (float*)d_out;
    fused_loss_kernel<<<GRID_A, THREADS_A>>>(x, out);
}

// round 13
// speedup vs baseline: 1.6996x; 1.4176x over previous
#include <cuda_runtime.h>
#include <math.h>

#define N_ROWS 8192
#define N_COLS 512
#define GRID_A 256
#define THREADS_A 256
#define WARPS_A 8              /* 256 blocks * 8 warps * 4 rows = 8192 rows */
#define NREP 8                 /* column replicas  */
#define SREP 64                /* scalar replicas  */

// Float accumulators (zero-init; last block resets).
__device__ float g_col[NREP][N_COLS];
__device__ float g_S[SREP];
__device__ int g_max_int[SREP];          // bit-cast float, values >= 0
__device__ unsigned int g_counter;

__global__ void __launch_bounds__(THREADS_A, 2)
fused_loss_kernel(const float* __restrict__ x, float* __restrict__ out) {
    __shared__ float s_colw[WARPS_A][N_COLS];   // 16 KB
    __shared__ float s_w[WARPS_A];
    __shared__ float s_sm[2];
    __shared__ float s_mx[2];
    __shared__ unsigned int s_last;

    const int tid = threadIdx.x;
    const int wid = tid >> 5;
    const int lid = tid & 31;

    // ---- warp owns 4 rows; 16 named float4 loads, ALL issued up front ----
    const int row0 = (blockIdx.x * WARPS_A + wid) * 4;
    const float4* p0 = reinterpret_cast<const float4*>(x + (size_t)row0 * N_COLS);
    const float4* p1 = p0 + 128;
    const float4* p2 = p0 + 256;
    const float4* p3 = p0 + 384;

    const float4 a0 = p0[lid];      const float4 a1 = p0[32 + lid];
    const float4 a2 = p0[64 + lid]; const float4 a3 = p0[96 + lid];
    const float4 b0 = p1[lid];      const float4 b1 = p1[32 + lid];
    const float4 b2 = p1[64 + lid]; const float4 b3 = p1[96 + lid];
    const float4 c0 = p2[lid];      const float4 c1 = p2[32 + lid];
    const float4 c2 = p2[64 + lid]; const float4 c3 = p2[96 + lid];
    const float4 d0 = p3[lid];      const float4 d1 = p3[32 + lid];
    const float4 d2 = p3[64 + lid]; const float4 d3 = p3[96 + lid];

    // column partials (4 rows summed) into smem
    float4 s0, s1, s2, s3;
    s0.x = (a0.x + b0.x) + (c0.x + d0.x);  s0.y = (a0.y + b0.y) + (c0.y + d0.y);
    s0.z = (a0.z + b0.z) + (c0.z + d0.z);  s0.w = (a0.w + b0.w) + (c0.w + d0.w);
    s1.x = (a1.x + b1.x) + (c1.x + d1.x);  s1.y = (a1.y + b1.y) + (c1.y + d1.y);
    s1.z = (a1.z + b1.z) + (c1.z + d1.z);  s1.w = (a1.w + b1.w) + (c1.w + d1.w);
    s2.x = (a2.x + b2.x) + (c2.x + d2.x);  s2.y = (a2.y + b2.y) + (c2.y + d2.y);
    s2.z = (a2.z + b2.z) + (c2.z + d2.z);  s2.w = (a2.w + b2.w) + (c2.w + d2.w);
    s3.x = (a3.x + b3.x) + (c3.x + d3.x);  s3.y = (a3.y + b3.y) + (c3.y + d3.y);
    s3.z = (a3.z + b3.z) + (c3.z + d3.z);  s3.w = (a3.w + b3.w) + (c3.w + d3.w);
    *reinterpret_cast<float4*>(&s_colw[wid][0   + lid * 4]) = s0;
    *reinterpret_cast<float4*>(&s_colw[wid][128 + lid * 4]) = s1;
    *reinterpret_cast<float4*>(&s_colw[wid][256 + lid * 4]) = s2;
    *reinterpret_cast<float4*>(&s_colw[wid][384 + lid * 4]) = s3;

    // per-row squared-norm lane partials
    float q0 = a0.x*a0.x + a0.y*a0.y + a0.z*a0.z + a0.w*a0.w
             + a1.x*a1.x + a1.y*a1.y + a1.z*a1.z + a1.w*a1.w
             + a2.x*a2.x + a2.y*a2.y + a2.z*a2.z + a2.w*a2.w
             + a3.x*a3.x + a3.y*a3.y + a3.z*a3.z + a3.w*a3.w;
    float q1 = b0.x*b0.x + b0.y*b0.y + b0.z*b0.z + b0.w*b0.w
             + b1.x*b1.x + b1.y*b1.y + b1.z*b1.z + b1.w*b1.w
             + b2.x*b2.x + b2.y*b2.y + b2.z*b2.z + b2.w*b2.w
             + b3.x*b3.x + b3.y*b3.y + b3.z*b3.z + b3.w*b3.w;
    float q2 = c0.x*c0.x + c0.y*c0.y + c0.z*c0.z + c0.w*c0.w
             + c1.x*c1.x + c1.y*c1.y + c1.z*c1.z + c1.w*c1.w
             + c2.x*c2.x + c2.y*c2.y + c2.z*c2.z + c2.w*c2.w
             + c3.x*c3.x + c3.y*c3.y + c3.z*c3.z + c3.w*c3.w;
    float q3 = d0.x*d0.x + d0.y*d0.y + d0.z*d0.z + d0.w*d0.w
             + d1.x*d1.x + d1.y*d1.y + d1.z*d1.z + d1.w*d1.w
             + d2.x*d2.x + d2.y*d2.y + d2.z*d2.z + d2.w*d2.w
             + d3.x*d3.x + d3.y*d3.y + d3.z*d3.z + d3.w*d3.w;

    #pragma unroll
    for (int off = 16; off > 0; off >>= 1) {
        q0 += __shfl_xor_sync(0xffffffffu, q0, off);
        q1 += __shfl_xor_sync(0xffffffffu, q1, off);
        q2 += __shfl_xor_sync(0xffffffffu, q2, off);
        q3 += __shfl_xor_sync(0xffffffffu, q3, off);
    }
    // fire-and-forget float REDs: per-warp S and max (replicated)
    if (lid == 0) {
        const int rs = (blockIdx.x * WARPS_A + wid) & (SREP - 1);
        atomicAdd(&g_S[rs], (q0 + q1) + (q2 + q3));
        atomicMax(&g_max_int[rs],
                  __float_as_int(fmaxf(fmaxf(q0, q1), fmaxf(q2, q3))));
    }
    __syncthreads();

    // ---- combine 8 warps, push float column REDs (fire-and-forget) ----
    const int rep = blockIdx.x & (NREP - 1);
    #pragma unroll
    for (int k = 0; k < 2; ++k) {
        const int c = tid + k * THREADS_A;
        float v = 0.f;
        #pragma unroll
        for (int w = 0; w < WARPS_A; ++w) v += s_colw[w][c];
        atomicAdd(&g_col[rep][c], v);
    }

    // ---- last-block-done election: single acq_rel atomic (no MEMBAR) ----
    if (tid == 0) {
        unsigned int prev;
        unsigned int* cp = &g_counter;
        asm volatile("atom.acq_rel.gpu.add.u32 %0, [%1], %2;"
                     : "=r"(prev) : "l"(cp), "r"(1u) : "memory");
        s_last = (prev == (unsigned int)(GRID_A - 1)) ? 1u : 0u;
    }
    __syncthreads();
    if (s_last == 0u) return;

    // ---- finalize (last block only): all-float, log-depth ----
    // column totals: thread owns cols tid and tid+256 (16 indep L2 loads)
    float f0 = 0.f, f1 = 0.f;
    #pragma unroll
    for (int r = 0; r < NREP; ++r) {
        f0 += g_col[r][tid];
        f1 += g_col[r][tid + THREADS_A];
    }
    float csq = f0 * f0 + f1 * f1;

    #pragma unroll
    for (int off = 16; off > 0; off >>= 1)
        csq += __shfl_xor_sync(0xffffffffu, csq, off);
    if (lid == 0) s_w[wid] = csq;

    // S and max from replicated scalars (warps 0 and 1)
    if (tid < SREP) {
        float Sp = g_S[tid];
        float Mp = __int_as_float(g_max_int[tid]);
        #pragma unroll
        for (int off = 16; off > 0; off >>= 1) {
            Sp += __shfl_xor_sync(0xffffffffu, Sp, off);
            Mp = fmaxf(Mp, __shfl_xor_sync(0xffffffffu, Mp, off));
        }
        if (lid == 0) { s_sm[wid] = Sp; s_mx[wid] = Mp; }
    }
    __syncthreads();

    if (wid == 0) {
        float w = (lid < WARPS_A) ? s_w[lid] : 0.f;
        #pragma unroll
        for (int off = 4; off > 0; off >>= 1)
            w += __shfl_xor_sync(0xffffffffu, w, off);
        if (lid == 0) {
            const float ssq_total = w;
            const float S_total = s_sm[0] + s_sm[1];
            const float maxsq = fmaxf(s_mx[0], s_mx[1]);
            const float numer = 8192.0f * S_total - ssq_total;
            const float norm = sqrtf(maxsq);
            const float count = 0.5f * (float)N_ROWS * (float)(N_ROWS - 1);
            out[0] = numer / (norm * count);
        }
    }
    // reset accumulators for next graph replay
    #pragma unroll
    for (int r = 0; r < NREP; ++r) {
        g_col[r][tid] = 0.f;
        g_col[r][tid + THREADS_A] = 0.f;
    }
    if (tid < SREP) {
        g_S[tid] = 0.f;
        g_max_int[tid] = 0;
    }
    if (tid == 0) g_counter = 0u;
}

extern "C" void kernel_launch(void* const* d_in, const int* in_sizes, int n_in,
                              void* d_out, int out_size) {
    (void)in_sizes; (void)n_in; (void)out_size;
    const float* x = (const float*)d_in[0];
    float* out = (float*)d_out;
    fused_loss_kernel<<<GRID_A, THREADS_A>>>(x, out);
}

// round 14
// speedup vs baseline: 1.7122x; 1.0074x over previous
#include <cuda_runtime.h>
#include <math.h>

#define N_ROWS 8192
#define N_COLS 512
#define GRID_A 128
#define THREADS_A 256
#define WARPS_A 8              /* 128 blocks * 8 warps * 8 rows = 8192 rows */
#define NREP 8                 /* column replicas  */
#define SREP 64                /* scalar replicas  */

// Float accumulators (zero-init; last block resets).
__device__ float g_col[NREP][N_COLS];
__device__ float g_S[SREP];
__device__ int g_max_int[SREP];          // bit-cast float, values >= 0
__device__ unsigned int g_counter;

__global__ void __launch_bounds__(THREADS_A, 2)
fused_loss_kernel(const float* __restrict__ x, float* __restrict__ out) {
    __shared__ float s_colw[WARPS_A][N_COLS];   // 16 KB
    __shared__ float s_w[WARPS_A];
    __shared__ float s_sm[2];
    __shared__ float s_mx[2];
    __shared__ unsigned int s_last;

    const int tid = threadIdx.x;
    const int wid = tid >> 5;
    const int lid = tid & 31;

    // ---- warp owns 8 rows: two batches of 4 rows, 16 loads per batch ----
    const int row0 = (blockIdx.x * WARPS_A + wid) * 8;

    float4 k0 = make_float4(0.f,0.f,0.f,0.f), k1 = k0, k2 = k0, k3 = k0;
    float Sacc = 0.f, Macc = 0.f;

    #pragma unroll
    for (int h = 0; h < 2; ++h) {
        const float4* p0 = reinterpret_cast<const float4*>(
            x + (size_t)(row0 + h * 4) * N_COLS);
        const float4* p1 = p0 + 128;
        const float4* p2 = p0 + 256;
        const float4* p3 = p0 + 384;

        const float4 a0 = p0[lid];      const float4 a1 = p0[32 + lid];
        const float4 a2 = p0[64 + lid]; const float4 a3 = p0[96 + lid];
        const float4 b0 = p1[lid];      const float4 b1 = p1[32 + lid];
        const float4 b2 = p1[64 + lid]; const float4 b3 = p1[96 + lid];
        const float4 c0 = p2[lid];      const float4 c1 = p2[32 + lid];
        const float4 c2 = p2[64 + lid]; const float4 c3 = p2[96 + lid];
        const float4 d0 = p3[lid];      const float4 d1 = p3[32 + lid];
        const float4 d2 = p3[64 + lid]; const float4 d3 = p3[96 + lid];

        // column partials accumulate in registers across batches
        k0.x += (a0.x + b0.x) + (c0.x + d0.x);  k0.y += (a0.y + b0.y) + (c0.y + d0.y);
        k0.z += (a0.z + b0.z) + (c0.z + d0.z);  k0.w += (a0.w + b0.w) + (c0.w + d0.w);
        k1.x += (a1.x + b1.x) + (c1.x + d1.x);  k1.y += (a1.y + b1.y) + (c1.y + d1.y);
        k1.z += (a1.z + b1.z) + (c1.z + d1.z);  k1.w += (a1.w + b1.w) + (c1.w + d1.w);
        k2.x += (a2.x + b2.x) + (c2.x + d2.x);  k2.y += (a2.y + b2.y) + (c2.y + d2.y);
        k2.z += (a2.z + b2.z) + (c2.z + d2.z);  k2.w += (a2.w + b2.w) + (c2.w + d2.w);
        k3.x += (a3.x + b3.x) + (c3.x + d3.x);  k3.y += (a3.y + b3.y) + (c3.y + d3.y);
        k3.z += (a3.z + b3.z) + (c3.z + d3.z);  k3.w += (a3.w + b3.w) + (c3.w + d3.w);

        // per-row squared-norm lane partials
        float q0 = a0.x*a0.x + a0.y*a0.y + a0.z*a0.z + a0.w*a0.w
                 + a1.x*a1.x + a1.y*a1.y + a1.z*a1.z + a1.w*a1.w
                 + a2.x*a2.x + a2.y*a2.y + a2.z*a2.z + a2.w*a2.w
                 + a3.x*a3.x + a3.y*a3.y + a3.z*a3.z + a3.w*a3.w;
        float q1 = b0.x*b0.x + b0.y*b0.y + b0.z*b0.z + b0.w*b0.w
                 + b1.x*b1.x + b1.y*b1.y + b1.z*b1.z + b1.w*b1.w
                 + b2.x*b2.x + b2.y*b2.y + b2.z*b2.z + b2.w*b2.w
                 + b3.x*b3.x + b3.y*b3.y + b3.z*b3.z + b3.w*b3.w;
        float q2 = c0.x*c0.x + c0.y*c0.y + c0.z*c0.z + c0.w*c0.w
                 + c1.x*c1.x + c1.y*c1.y + c1.z*c1.z + c1.w*c1.w
                 + c2.x*c2.x + c2.y*c2.y + c2.z*c2.z + c2.w*c2.w
                 + c3.x*c3.x + c3.y*c3.y + c3.z*c3.z + c3.w*c3.w;
        float q3 = d0.x*d0.x + d0.y*d0.y + d0.z*d0.z + d0.w*d0.w
                 + d1.x*d1.x + d1.y*d1.y + d1.z*d1.z + d1.w*d1.w
                 + d2.x*d2.x + d2.y*d2.y + d2.z*d2.z + d2.w*d2.w
                 + d3.x*d3.x + d3.y*d3.y + d3.z*d3.z + d3.w*d3.w;

        #pragma unroll
        for (int off = 16; off > 0; off >>= 1) {
            q0 += __shfl_xor_sync(0xffffffffu, q0, off);
            q1 += __shfl_xor_sync(0xffffffffu, q1, off);
            q2 += __shfl_xor_sync(0xffffffffu, q2, off);
            q3 += __shfl_xor_sync(0xffffffffu, q3, off);
        }
        Sacc += (q0 + q1) + (q2 + q3);
        Macc = fmaxf(Macc, fmaxf(fmaxf(q0, q1), fmaxf(q2, q3)));
    }

    // single smem write per warp
    *reinterpret_cast<float4*>(&s_colw[wid][0   + lid * 4]) = k0;
    *reinterpret_cast<float4*>(&s_colw[wid][128 + lid * 4]) = k1;
    *reinterpret_cast<float4*>(&s_colw[wid][256 + lid * 4]) = k2;
    *reinterpret_cast<float4*>(&s_colw[wid][384 + lid * 4]) = k3;

    // fire-and-forget float REDs: per-warp S and max (replicated)
    if (lid == 0) {
        const int rs = (blockIdx.x * WARPS_A + wid) & (SREP - 1);
        atomicAdd(&g_S[rs], Sacc);
        atomicMax(&g_max_int[rs], __float_as_int(Macc));
    }
    __syncthreads();

    // ---- combine 8 warps, push float column REDs (fire-and-forget) ----
    const int rep = blockIdx.x & (NREP - 1);
    #pragma unroll
    for (int k = 0; k < 2; ++k) {
        const int c = tid + k * THREADS_A;
        float v = 0.f;
        #pragma unroll
        for (int w = 0; w < WARPS_A; ++w) v += s_colw[w][c];
        atomicAdd(&g_col[rep][c], v);
    }

    // ---- last-block-done election: single acq_rel atomic (no MEMBAR) ----
    if (tid == 0) {
        unsigned int prev;
        unsigned int* cp = &g_counter;
        asm volatile("atom.acq_rel.gpu.add.u32 %0, [%1], %2;"
                     : "=r"(prev) : "l"(cp), "r"(1u) : "memory");
        s_last = (prev == (unsigned int)(GRID_A - 1)) ? 1u : 0u;
    }
    __syncthreads();
    if (s_last == 0u) return;

    // ---- finalize (last block only): all-float, log-depth ----
    float f0 = 0.f, f1 = 0.f;
    #pragma unroll
    for (int r = 0; r < NREP; ++r) {
        f0 += g_col[r][tid];
        f1 += g_col[r][tid + THREADS_A];
    }
    float csq = f0 * f0 + f1 * f1;

    #pragma unroll
    for (int off = 16; off > 0; off >>= 1)
        csq += __shfl_xor_sync(0xffffffffu, csq, off);
    if (lid == 0) s_w[wid] = csq;

    if (tid < SREP) {
        float Sp = g_S[tid];
        float Mp = __int_as_float(g_max_int[tid]);
        #pragma unroll
        for (int off = 16; off > 0; off >>= 1) {
            Sp += __shfl_xor_sync(0xffffffffu, Sp, off);
            Mp = fmaxf(Mp, __shfl_xor_sync(0xffffffffu, Mp, off));
        }
        if (lid == 0) { s_sm[wid] = Sp; s_mx[wid] = Mp; }
    }
    __syncthreads();

    if (wid == 0) {
        float w = (lid < WARPS_A) ? s_w[lid] : 0.f;
        #pragma unroll
        for (int off = 4; off > 0; off >>= 1)
            w += __shfl_xor_sync(0xffffffffu, w, off);
        if (lid == 0) {
            const float ssq_total = w;
            const float S_total = s_sm[0] + s_sm[1];
            const float maxsq = fmaxf(s_mx[0], s_mx[1]);
            const float numer = 8192.0f * S_total - ssq_total;
            const float norm = sqrtf(maxsq);
            const float count = 0.5f * (float)N_ROWS * (float)(N_ROWS - 1);
            out[0] = numer / (norm * count);
        }
    }
    // reset accumulators for next graph replay
    #pragma unroll
    for (int r = 0; r < NREP; ++r) {
        g_col[r][tid] = 0.f;
        g_col[r][tid + THREADS_A] = 0.f;
    }
    if (tid < SREP) {
        g_S[tid] = 0.f;
        g_max_int[tid] = 0;
    }
    if (tid == 0) g_counter = 0u;
}

extern "C" void kernel_launch(void* const* d_in, const int* in_sizes, int n_in,
                              void* d_out, int out_size) {
    (void)in_sizes; (void)n_in; (void)out_size;
    const float* x = (const float*)d_in[0];
    float* out = (float*)d_out;
    fused_loss_kernel<<<GRID_A, THREADS_A>>>(x, out);
}